// round 2
// baseline (speedup 1.0000x reference)
#include <cuda_runtime.h>

// Path_Embedding fused kernel, round 2: channel-packed f32x2 tiling.
//
// out[b][c] = bias[c] + max_{a<16, w<4} sum_j e[a][w][j]*W0[c][j] + e[a][w+1][j]*W1[c][j]
// with e[a][t] = tables[path_type[t]][ path_input[a*512 + b/16, b%16, t] ]
//
// Block = 128 threads = 16 a-rows x 8 channel-groups; loops over 4 b-rows.
// Accumulators packed over CHANNELS (f32x2) -> weight LDS reads are contiguous
// 128B rows (1 wavefront), e reads are 4-way-broadcast bank-spread (1 wavefront).

typedef unsigned long long u64;

#define VOCAB 100000
#define NBPB  4
#define EPAD  68          // e row stride (floats): 272B, 16B-aligned, bank-spread
#define RPAD  68

#define SM_E   0
#define SM_W0  21760      // 16*5*68*4
#define SM_W1  38144      // + 64*64*4
#define SM_RED 54528      // + 64*64*4
#define SM_IDX 58880      // + 16*68*4
#define SM_TOT 59200      // + 80*4

__device__ __forceinline__ void ffma2(u64 &d, u64 a, u64 b) {
    asm("fma.rn.f32x2 %0, %1, %2, %0;" : "+l"(d) : "l"(a), "l"(b));
}
__device__ __forceinline__ u64 dup2(float v) {
    u64 r;
    asm("mov.b64 %0, {%1, %1};" : "=l"(r) : "f"(v));
    return r;
}

__global__ __launch_bounds__(128, 3) void path_emb_kernel(
    const int*   __restrict__ path_input,   // [8192,16,5]
    const int*   __restrict__ path_type,    // [5]
    const float* __restrict__ tables,       // [3,100000,64]
    const float* __restrict__ conv_w,       // [64,64,2]
    const float* __restrict__ conv_b,       // [64]
    float*       __restrict__ out)          // [8192,64]
{
    extern __shared__ char smem_raw[];
    float (*e_s)[5][EPAD] = reinterpret_cast<float(*)[5][EPAD]>(smem_raw + SM_E);
    float (*w0s)[64]      = reinterpret_cast<float(*)[64]>(smem_raw + SM_W0);
    float (*w1s)[64]      = reinterpret_cast<float(*)[64]>(smem_raw + SM_W1);
    float (*red)[RPAD]    = reinterpret_cast<float(*)[RPAD]>(smem_raw + SM_RED);
    int   (*idx_s)[5]     = reinterpret_cast<int(*)[5]>(smem_raw + SM_IDX);

    const int tid = threadIdx.x;

    // ---- stage weights once per block, transposed to [j][o] ----
    const float2* cw2 = reinterpret_cast<const float2*>(conv_w);
    #pragma unroll
    for (int it = 0; it < 32; it++) {
        int i = tid + it * 128;            // i = o*64 + j
        int o = i >> 6, j = i & 63;
        float2 wv = cw2[i];                // (W0[o][j], W1[o][j])
        w0s[j][o] = wv.x;
        w1s[j][o] = wv.y;
    }

    const int a  = tid >> 3;               // 0..15 (warp: 4 consecutive a)
    const int og = tid & 7;                // 8-channel group

    for (int ib = 0; ib < NBPB; ib++) {
        const int b  = blockIdx.x * NBPB + ib;
        const int p  = b & 15;
        const int nb = b >> 4;

        __syncthreads();                    // prev compute done; safe to overwrite
        if (tid < 80) {
            int aa = tid / 5, t = tid - aa * 5;
            int raw = path_input[(((aa << 9) + nb) * 16 + p) * 5 + t];
            idx_s[aa][t] = __ldg(&path_type[t]) * VOCAB + raw;
        }
        __syncthreads();

        // ---- gather 80 embedding rows (float4 vectorized) ----
        const float4* tab4 = reinterpret_cast<const float4*>(tables);
        #pragma unroll
        for (int it = 0; it < 10; it++) {
            int k = tid + it * 128;         // 1280 float4 total
            int row = k >> 4, q = k & 15;
            int aa = row / 5, t = row - aa * 5;
            float4 v = __ldg(&tab4[(long long)idx_s[aa][t] * 16 + q]);
            *reinterpret_cast<float4*>(&e_s[aa][t][q * 4]) = v;
        }
        __syncthreads();

        // ---- conv + window accumulation, channels packed f32x2 ----
        u64 s[4][4];                        // [window][channel-pair]
        #pragma unroll
        for (int w = 0; w < 4; w++)
            #pragma unroll
            for (int oo = 0; oo < 4; oo++) s[w][oo] = 0ull;

        #pragma unroll 2
        for (int jj = 0; jj < 16; jj++) {
            float4 ef[5];
            #pragma unroll
            for (int t = 0; t < 5; t++)     // 1 wavefront each (bank-spread a)
                ef[t] = *reinterpret_cast<const float4*>(&e_s[a][t][jj << 2]);

            #pragma unroll
            for (int js = 0; js < 4; js++) {
                const int j = (jj << 2) + js;
                // contiguous 128B rows -> 1 wavefront per LDS.128
                const ulonglong2 w0lo = *reinterpret_cast<const ulonglong2*>(&w0s[j][og * 8]);
                const ulonglong2 w0hi = *reinterpret_cast<const ulonglong2*>(&w0s[j][og * 8 + 4]);
                const ulonglong2 w1lo = *reinterpret_cast<const ulonglong2*>(&w1s[j][og * 8]);
                const ulonglong2 w1hi = *reinterpret_cast<const ulonglong2*>(&w1s[j][og * 8 + 4]);

                u64 vd[5];
                #pragma unroll
                for (int t = 0; t < 5; t++) {
                    float ev = (js == 0) ? ef[t].x : (js == 1) ? ef[t].y
                             : (js == 2) ? ef[t].z : ef[t].w;
                    vd[t] = dup2(ev);
                }
                // window w gets e[w]*W0 ...
                #pragma unroll
                for (int t = 0; t < 4; t++) {
                    ffma2(s[t][0], vd[t], w0lo.x);
                    ffma2(s[t][1], vd[t], w0lo.y);
                    ffma2(s[t][2], vd[t], w0hi.x);
                    ffma2(s[t][3], vd[t], w0hi.y);
                }
                // ... and e[w+1]*W1
                #pragma unroll
                for (int t = 1; t < 5; t++) {
                    ffma2(s[t - 1][0], vd[t], w1lo.x);
                    ffma2(s[t - 1][1], vd[t], w1lo.y);
                    ffma2(s[t - 1][2], vd[t], w1hi.x);
                    ffma2(s[t - 1][3], vd[t], w1hi.y);
                }
            }
        }

        // ---- max over windows; stash per-a channel maxima ----
        #pragma unroll
        for (int oo = 0; oo < 4; oo++) {
            float mlo = -3.402823466e38f, mhi = -3.402823466e38f;
            #pragma unroll
            for (int w = 0; w < 4; w++) {
                mlo = fmaxf(mlo, __uint_as_float((unsigned)s[w][oo]));
                mhi = fmaxf(mhi, __uint_as_float((unsigned)(s[w][oo] >> 32)));
            }
            red[a][og * 8 + 2 * oo]     = mlo;
            red[a][og * 8 + 2 * oo + 1] = mhi;
        }
        __syncthreads();

        // ---- max over the 16 a-rows, add bias, store ----
        if (tid < 64) {
            float m = red[0][tid];
            #pragma unroll
            for (int aa = 1; aa < 16; aa++) m = fmaxf(m, red[aa][tid]);
            out[(long long)b * 64 + tid] = m + __ldg(&conv_b[tid]);
        }
    }
}

extern "C" void kernel_launch(void* const* d_in, const int* in_sizes, int n_in,
                              void* d_out, int out_size) {
    const int*   path_input = (const int*)d_in[0];
    const int*   path_type  = (const int*)d_in[1];
    const float* tables     = (const float*)d_in[2];
    const float* conv_w     = (const float*)d_in[3];
    const float* conv_b     = (const float*)d_in[4];
    float* out = (float*)d_out;

    cudaFuncSetAttribute(path_emb_kernel,
                         cudaFuncAttributeMaxDynamicSharedMemorySize, SM_TOT);

    path_emb_kernel<<<8192 / NBPB, 128, SM_TOT>>>(path_input, path_type, tables,
                                                  conv_w, conv_b, out);
}

// round 4
// speedup vs baseline: 1.9222x; 1.9222x over previous
#include <cuda_runtime.h>
#include <cuda_bf16.h>
#include <cstdint>

// Path_Embedding via base-ISA mma.sync (bf16, 3-term hi/lo split fp32 emulation).
// Per tile (2 output rows): S[128 x 64] = E'(128x128) @ W'^T(64x128),
//   S ~= Eh*Wh + El*Wh + Eh*Wl   (each operand split x = hi(bf16) + lo(bf16))
// then out[b][c] = bias[c] + max over the 64 (a,w)-rows of b.
//   E' row (b2,a,w): k<64 -> e[b2,a][t=w][k], k>=64 -> e[b2,a][t=w+1][k-64]
//   W' row o:        k<64 -> W0[o][k],        k>=64 -> W1[o][k-64]
// Block = 128 threads (4 warps), 1 tile; warp w owns m-rows [32w, 32w+32).
// grid = 4096. Row stride 272B (odd multiple of 16B) -> conflict-free ldmatrix.

#define VOCAB 100000
#define RS 272                 // bytes per k-row (136 bf16)

#define EH_OFF  0              // 128*272 = 34816
#define EL_OFF  34816
#define WH_OFF  69632          // 64*272 = 17408
#define WL_OFF  87040
#define IDX_OFF 104448         // 160 * 4
#define RED_OFF 105088         // 4 * 64 * 4
#define SM_TOT  106112

typedef unsigned long long u64;

__device__ __forceinline__ uint32_t smem_u32(const void* p) {
    uint32_t a;
    asm("{ .reg .u64 t; cvta.to.shared.u64 t, %1; cvt.u32.u64 %0, t; }" : "=r"(a) : "l"(p));
    return a;
}

#define LDMX4(r, addr)                                                        \
    asm volatile("ldmatrix.sync.aligned.m8n8.x4.shared.b16 {%0,%1,%2,%3}, [%4];" \
        : "=r"((r)[0]), "=r"((r)[1]), "=r"((r)[2]), "=r"((r)[3]) : "r"(addr))

#define MMA(d, a, b0, b1)                                                     \
    asm volatile("mma.sync.aligned.m16n8k16.row.col.f32.bf16.bf16.f32 "       \
        "{%0,%1,%2,%3},{%4,%5,%6,%7},{%8,%9},{%0,%1,%2,%3};"                  \
        : "+f"((d)[0]), "+f"((d)[1]), "+f"((d)[2]), "+f"((d)[3])              \
        : "r"((a)[0]), "r"((a)[1]), "r"((a)[2]), "r"((a)[3]),                 \
          "r"(b0), "r"(b1))

// split 4 floats into packed bf16x2 hi (returned) and lo (out-param)
__device__ __forceinline__ u64 pack_hi_lo(float x, float y, float z, float w,
                                          u64& lo_out) {
    __nv_bfloat162 h01 = __float22bfloat162_rn(make_float2(x, y));
    __nv_bfloat162 h23 = __float22bfloat162_rn(make_float2(z, w));
    float2 f01 = __bfloat1622float2(h01);
    float2 f23 = __bfloat1622float2(h23);
    __nv_bfloat162 l01 = __float22bfloat162_rn(make_float2(x - f01.x, y - f01.y));
    __nv_bfloat162 l23 = __float22bfloat162_rn(make_float2(z - f23.x, w - f23.y));
    uint32_t h0 = *reinterpret_cast<uint32_t*>(&h01);
    uint32_t h1 = *reinterpret_cast<uint32_t*>(&h23);
    uint32_t l0 = *reinterpret_cast<uint32_t*>(&l01);
    uint32_t l1 = *reinterpret_cast<uint32_t*>(&l23);
    lo_out = (u64)l0 | ((u64)l1 << 32);
    return (u64)h0 | ((u64)h1 << 32);
}

__global__ __launch_bounds__(128, 2) void path_emb_hmma(
    const int*   __restrict__ path_input,   // [8192,16,5]
    const int*   __restrict__ path_type,    // [5]
    const float* __restrict__ tables,       // [3,100000,64]
    const float* __restrict__ conv_w,       // [64,64,2]
    const float* __restrict__ conv_b,       // [64]
    float*       __restrict__ out)          // [8192,64]
{
    extern __shared__ char smem[];
    const uint32_t sb = smem_u32(smem);
    const int tid  = threadIdx.x;
    const int lane = tid & 31;
    const int wid  = tid >> 5;
    const int tile = blockIdx.x;

    int*  idx_s     = reinterpret_cast<int*>(smem + IDX_OFF);
    float (*red)[64] = reinterpret_cast<float(*)[64]>(smem + RED_OFF);

    // ---- stage indices (160 rows: 2 b x 16 a x 5 t) ----
    #pragma unroll
    for (int r = tid; r < 160; r += 128) {
        int b2 = r / 80, rr = r % 80, a = rr / 5, t = rr % 5;
        int b = tile * 2 + b2, p = b & 15, nb = b >> 4;
        int raw = path_input[(((a << 9) + nb) * 16 + p) * 5 + t];
        idx_s[r] = __ldg(&path_type[t]) * VOCAB + raw;
    }

    // ---- stage W', hi/lo split, [o][k] rows of 272B ----
    {
        const float4* cw4 = reinterpret_cast<const float4*>(conv_w);
        int o = tid >> 1, j0 = (tid & 1) * 32;
        #pragma unroll
        for (int jj = 0; jj < 32; jj += 4) {
            int j = j0 + jj;
            float4 v0 = __ldg(&cw4[o * 32 + (j >> 1)]);      // (W0[j],W1[j],W0[j+1],W1[j+1])
            float4 v1 = __ldg(&cw4[o * 32 + (j >> 1) + 1]);  // (W0[j+2],...)
            u64 L0, H0 = pack_hi_lo(v0.x, v0.z, v1.x, v1.z, L0);  // tap0, k=j..j+3
            u64 L1, H1 = pack_hi_lo(v0.y, v0.w, v1.y, v1.w, L1);  // tap1, k=64+j..
            *reinterpret_cast<u64*>(smem + WH_OFF + o * RS + j * 2)        = H0;
            *reinterpret_cast<u64*>(smem + WL_OFF + o * RS + j * 2)        = L0;
            *reinterpret_cast<u64*>(smem + WH_OFF + o * RS + 128 + j * 2)  = H1;
            *reinterpret_cast<u64*>(smem + WL_OFF + o * RS + 128 + j * 2)  = L1;
        }
    }
    __syncthreads();

    // ---- gather E (160 rows x 16 float4), hi/lo split, scatter to E' ----
    const float4* tab4 = reinterpret_cast<const float4*>(tables);
    #pragma unroll
    for (int g = 0; g < 20; g++) {
        int k = tid + g * 128;               // 2560 total
        int row = k >> 4, q = k & 15;
        float4 v = __ldg(&tab4[(long long)idx_s[row] * 16 + q]);
        u64 L, H = pack_hi_lo(v.x, v.y, v.z, v.w, L);
        int b2 = row / 80, rr = row % 80, a = rr / 5, t = rr % 5;
        int mb = b2 * 64 + a * 4;
        if (t < 4) {                          // window w=t, tap0: k = q*4
            int off = (mb + t) * RS + q * 8;
            *reinterpret_cast<u64*>(smem + EH_OFF + off) = H;
            *reinterpret_cast<u64*>(smem + EL_OFF + off) = L;
        }
        if (t >= 1) {                         // window w=t-1, tap1: k = 64 + q*4
            int off = (mb + t - 1) * RS + 128 + q * 8;
            *reinterpret_cast<u64*>(smem + EH_OFF + off) = H;
            *reinterpret_cast<u64*>(smem + EL_OFF + off) = L;
        }
    }
    __syncthreads();

    // ---- mma: warp owns m-rows [32*wid, 32*wid+32) ----
    const int m0 = wid * 32;
    // A lanes: rows m0+(lane&15), col-half (lane>>4)
    const uint32_t aoff = (uint32_t)((m0 + (lane & 15)) * RS + (lane >> 4) * 16);
    // B lanes: n = (lane&7) + 8*(lane>>4), k-half ((lane>>3)&1)
    const uint32_t boff = (uint32_t)(((lane & 7) + ((lane >> 4) << 3)) * RS
                                     + ((lane >> 3) & 1) * 16);
    const uint32_t sEh = sb + EH_OFF + aoff, sEl = sb + EL_OFF + aoff;
    const uint32_t sWh = sb + WH_OFF + boff, sWl = sb + WL_OFF + boff;

    float d[8][8];                            // [n-tile][m-tile*4 + reg]
    #pragma unroll
    for (int nt = 0; nt < 8; nt++)
        #pragma unroll
        for (int r = 0; r < 8; r++) d[nt][r] = 0.f;

    #pragma unroll 2
    for (int ks = 0; ks < 8; ks++) {
        const uint32_t kb = ks * 32;          // 16 bf16 per k-step
        uint32_t ah[8], al[8], bh[16], bl[16];
        LDMX4(&ah[0], sEh + kb);
        LDMX4(&ah[4], sEh + kb + 16 * RS);
        LDMX4(&al[0], sEl + kb);
        LDMX4(&al[4], sEl + kb + 16 * RS);
        #pragma unroll
        for (int g = 0; g < 4; g++) LDMX4(&bh[4 * g], sWh + kb + g * 16 * RS);
        #pragma unroll
        for (int g = 0; g < 4; g++) LDMX4(&bl[4 * g], sWl + kb + g * 16 * RS);

        #pragma unroll
        for (int nt = 0; nt < 8; nt++) {
            const int bi = (nt >> 1) * 4 + (nt & 1) * 2;
            MMA(&d[nt][0], &ah[0], bh[bi], bh[bi + 1]);  // Eh*Wh
            MMA(&d[nt][4], &ah[4], bh[bi], bh[bi + 1]);
            MMA(&d[nt][0], &al[0], bh[bi], bh[bi + 1]);  // El*Wh
            MMA(&d[nt][4], &al[4], bh[bi], bh[bi + 1]);
            MMA(&d[nt][0], &ah[0], bl[bi], bl[bi + 1]);  // Eh*Wl
            MMA(&d[nt][4], &ah[4], bl[bi], bl[bi + 1]);
        }
    }

    // ---- epilogue: max over this warp's 32 m-rows per column ----
    // D frag: c0,c1 = row lane/4, cols (lane%4)*2+{0,1}; c2,c3 = row lane/4+8.
    #pragma unroll
    for (int nt = 0; nt < 8; nt++) {
        float v0 = fmaxf(fmaxf(d[nt][0], d[nt][2]), fmaxf(d[nt][4], d[nt][6]));
        float v1 = fmaxf(fmaxf(d[nt][1], d[nt][3]), fmaxf(d[nt][5], d[nt][7]));
        #pragma unroll
        for (int mask = 4; mask <= 16; mask <<= 1) {     // reduce over lane/4
            v0 = fmaxf(v0, __shfl_xor_sync(0xffffffffu, v0, mask));
            v1 = fmaxf(v1, __shfl_xor_sync(0xffffffffu, v1, mask));
        }
        if (lane < 4) {
            red[wid][nt * 8 + lane * 2]     = v0;
            red[wid][nt * 8 + lane * 2 + 1] = v1;
        }
    }
    __syncthreads();

    // ---- final: max over the 2 warps per b2 (warps 0,1 -> b2=0; 2,3 -> b2=1) ----
    {
        int b2 = tid >> 6, c = tid & 63;
        float m = fmaxf(red[b2 * 2][c], red[b2 * 2 + 1][c]);
        out[(long long)(tile * 2 + b2) * 64 + c] = m + __ldg(&conv_b[c]);
    }
}

extern "C" void kernel_launch(void* const* d_in, const int* in_sizes, int n_in,
                              void* d_out, int out_size) {
    const int*   path_input = (const int*)d_in[0];
    const int*   path_type  = (const int*)d_in[1];
    const float* tables     = (const float*)d_in[2];
    const float* conv_w     = (const float*)d_in[3];
    const float* conv_b     = (const float*)d_in[4];
    float* out = (float*)d_out;

    cudaFuncSetAttribute(path_emb_hmma,
                         cudaFuncAttributeMaxDynamicSharedMemorySize, SM_TOT);

    path_emb_hmma<<<4096, 128, SM_TOT>>>(path_input, path_type, tables,
                                         conv_w, conv_b, out);
}

// round 5
// speedup vs baseline: 2.3462x; 1.2206x over previous
#include <cuda_runtime.h>
#include <cuda_bf16.h>
#include <cstdint>

// Path_Embedding via base-ISA mma.sync (bf16, 3-term hi/lo split fp32 emulation).
// Per tile (2 output rows): S[128 x 64] = E'(128x128) @ W'^T(64x128),
//   S ~= Eh*Wh + El*Wh + Eh*Wl
// then out[b][c] = bias[c] + max over the 64 (a,w)-rows of b.
// Round 5: 256 threads / 8 warps per block (16 m-rows per warp) to double
// occupancy (16 warps/SM) and hide gather + ldmatrix + mma latency.

#define VOCAB 100000
#define RS 272                 // bytes per k-row (136 bf16): odd 16B multiple

#define EH_OFF  0              // 128*272 = 34816
#define EL_OFF  34816
#define WH_OFF  69632          // 64*272 = 17408
#define WL_OFF  87040
#define IDX_OFF 104448         // 160 * 4
#define RED_OFF 105088         // 8 * 64 * 4
#define SM_TOT  107136

typedef unsigned long long u64;

__device__ __forceinline__ uint32_t smem_u32(const void* p) {
    uint32_t a;
    asm("{ .reg .u64 t; cvta.to.shared.u64 t, %1; cvt.u32.u64 %0, t; }" : "=r"(a) : "l"(p));
    return a;
}

#define LDMX4(r, addr)                                                        \
    asm volatile("ldmatrix.sync.aligned.m8n8.x4.shared.b16 {%0,%1,%2,%3}, [%4];" \
        : "=r"((r)[0]), "=r"((r)[1]), "=r"((r)[2]), "=r"((r)[3]) : "r"(addr))

#define MMA(d, a, b0, b1)                                                     \
    asm volatile("mma.sync.aligned.m16n8k16.row.col.f32.bf16.bf16.f32 "       \
        "{%0,%1,%2,%3},{%4,%5,%6,%7},{%8,%9},{%0,%1,%2,%3};"                  \
        : "+f"((d)[0]), "+f"((d)[1]), "+f"((d)[2]), "+f"((d)[3])              \
        : "r"((a)[0]), "r"((a)[1]), "r"((a)[2]), "r"((a)[3]),                 \
          "r"(b0), "r"(b1))

// split 4 floats into packed bf16x2 hi (returned) and lo (out-param)
__device__ __forceinline__ u64 pack_hi_lo(float x, float y, float z, float w,
                                          u64& lo_out) {
    __nv_bfloat162 h01 = __float22bfloat162_rn(make_float2(x, y));
    __nv_bfloat162 h23 = __float22bfloat162_rn(make_float2(z, w));
    float2 f01 = __bfloat1622float2(h01);
    float2 f23 = __bfloat1622float2(h23);
    __nv_bfloat162 l01 = __float22bfloat162_rn(make_float2(x - f01.x, y - f01.y));
    __nv_bfloat162 l23 = __float22bfloat162_rn(make_float2(z - f23.x, w - f23.y));
    uint32_t h0 = *reinterpret_cast<uint32_t*>(&h01);
    uint32_t h1 = *reinterpret_cast<uint32_t*>(&h23);
    uint32_t l0 = *reinterpret_cast<uint32_t*>(&l01);
    uint32_t l1 = *reinterpret_cast<uint32_t*>(&l23);
    lo_out = (u64)l0 | ((u64)l1 << 32);
    return (u64)h0 | ((u64)h1 << 32);
}

__global__ __launch_bounds__(256, 2) void path_emb_hmma(
    const int*   __restrict__ path_input,   // [8192,16,5]
    const int*   __restrict__ path_type,    // [5]
    const float* __restrict__ tables,       // [3,100000,64]
    const float* __restrict__ conv_w,       // [64,64,2]
    const float* __restrict__ conv_b,       // [64]
    float*       __restrict__ out)          // [8192,64]
{
    extern __shared__ char smem[];
    const uint32_t sb = smem_u32(smem);
    const int tid  = threadIdx.x;
    const int lane = tid & 31;
    const int wid  = tid >> 5;
    const int tile = blockIdx.x;

    int*  idx_s      = reinterpret_cast<int*>(smem + IDX_OFF);
    float (*red)[64] = reinterpret_cast<float(*)[64]>(smem + RED_OFF);

    // ---- stage indices (160 rows: 2 b x 16 a x 5 t) ----
    if (tid < 160) {
        int b2 = tid / 80, rr = tid % 80, a = rr / 5, t = rr % 5;
        int b = tile * 2 + b2, p = b & 15, nb = b >> 4;
        int raw = path_input[(((a << 9) + nb) * 16 + p) * 5 + t];
        idx_s[tid] = __ldg(&path_type[t]) * VOCAB + raw;
    }

    // ---- stage W', hi/lo split, [o][k] rows of 272B ----
    {
        const float4* cw4 = reinterpret_cast<const float4*>(conv_w);
        int o = tid >> 2, j0 = (tid & 3) * 16;
        #pragma unroll
        for (int jj = 0; jj < 16; jj += 4) {
            int j = j0 + jj;
            float4 v0 = __ldg(&cw4[o * 32 + (j >> 1)]);      // (W0[j],W1[j],W0[j+1],W1[j+1])
            float4 v1 = __ldg(&cw4[o * 32 + (j >> 1) + 1]);
            u64 L0, H0 = pack_hi_lo(v0.x, v0.z, v1.x, v1.z, L0);  // tap0: k=j..j+3
            u64 L1, H1 = pack_hi_lo(v0.y, v0.w, v1.y, v1.w, L1);  // tap1: k=64+j..
            *reinterpret_cast<u64*>(smem + WH_OFF + o * RS + j * 2)        = H0;
            *reinterpret_cast<u64*>(smem + WL_OFF + o * RS + j * 2)        = L0;
            *reinterpret_cast<u64*>(smem + WH_OFF + o * RS + 128 + j * 2)  = H1;
            *reinterpret_cast<u64*>(smem + WL_OFF + o * RS + 128 + j * 2)  = L1;
        }
    }
    __syncthreads();

    // ---- gather E (160 rows x 16 float4), hi/lo split, scatter to E' ----
    const float4* tab4 = reinterpret_cast<const float4*>(tables);
    #pragma unroll
    for (int g = 0; g < 10; g++) {
        int k = tid + g * 256;               // 2560 total
        int row = k >> 4, q = k & 15;
        float4 v = __ldg(&tab4[(long long)idx_s[row] * 16 + q]);
        u64 L, H = pack_hi_lo(v.x, v.y, v.z, v.w, L);
        int b2 = row / 80, rr = row % 80, a = rr / 5, t = rr % 5;
        int mb = b2 * 64 + a * 4;
        if (t < 4) {                          // window w=t, tap0: k = q*4
            int off = (mb + t) * RS + q * 8;
            *reinterpret_cast<u64*>(smem + EH_OFF + off) = H;
            *reinterpret_cast<u64*>(smem + EL_OFF + off) = L;
        }
        if (t >= 1) {                         // window w=t-1, tap1: k = 64 + q*4
            int off = (mb + t - 1) * RS + 128 + q * 8;
            *reinterpret_cast<u64*>(smem + EH_OFF + off) = H;
            *reinterpret_cast<u64*>(smem + EL_OFF + off) = L;
        }
    }
    __syncthreads();

    // ---- mma: warp owns m-rows [16*wid, 16*wid+16) ----
    const int m0 = wid * 16;
    const uint32_t aoff = (uint32_t)((m0 + (lane & 15)) * RS + (lane >> 4) * 16);
    const uint32_t boff = (uint32_t)(((lane & 7) + ((lane >> 4) << 3)) * RS
                                     + ((lane >> 3) & 1) * 16);
    const uint32_t sEh = sb + EH_OFF + aoff, sEl = sb + EL_OFF + aoff;
    const uint32_t sWh = sb + WH_OFF + boff, sWl = sb + WL_OFF + boff;

    float d[8][4];                            // [n-tile][reg]
    #pragma unroll
    for (int nt = 0; nt < 8; nt++)
        #pragma unroll
        for (int r = 0; r < 4; r++) d[nt][r] = 0.f;

    #pragma unroll 2
    for (int ks = 0; ks < 8; ks++) {
        const uint32_t kb = ks * 32;          // 16 bf16 per k-step
        uint32_t ah[4], al[4], bh[16], bl[16];
        LDMX4(ah, sEh + kb);
        LDMX4(al, sEl + kb);
        #pragma unroll
        for (int g = 0; g < 4; g++) LDMX4(&bh[4 * g], sWh + kb + g * 16 * RS);
        #pragma unroll
        for (int g = 0; g < 4; g++) LDMX4(&bl[4 * g], sWl + kb + g * 16 * RS);

        #pragma unroll
        for (int nt = 0; nt < 8; nt++) {
            const int bi = (nt >> 1) * 4 + (nt & 1) * 2;
            MMA(d[nt], ah, bh[bi], bh[bi + 1]);   // Eh*Wh
            MMA(d[nt], al, bh[bi], bh[bi + 1]);   // El*Wh
            MMA(d[nt], ah, bl[bi], bl[bi + 1]);   // Eh*Wl
        }
    }

    // ---- epilogue: max over this warp's 16 m-rows per column ----
    // D frag: c0,c1 = row lane/4, cols (lane%4)*2+{0,1}; c2,c3 = row lane/4+8.
    #pragma unroll
    for (int nt = 0; nt < 8; nt++) {
        float v0 = fmaxf(d[nt][0], d[nt][2]);
        float v1 = fmaxf(d[nt][1], d[nt][3]);
        #pragma unroll
        for (int mask = 4; mask <= 16; mask <<= 1) {     // reduce over lane/4
            v0 = fmaxf(v0, __shfl_xor_sync(0xffffffffu, v0, mask));
            v1 = fmaxf(v1, __shfl_xor_sync(0xffffffffu, v1, mask));
        }
        if (lane < 4) {
            red[wid][nt * 8 + lane * 2]     = v0;
            red[wid][nt * 8 + lane * 2 + 1] = v1;
        }
    }
    __syncthreads();

    // ---- final: warps 0-3 cover b2=0 (m 0..63), warps 4-7 b2=1 ----
    if (tid < 128) {
        int b2 = tid >> 6, c = tid & 63;
        float m = fmaxf(fmaxf(red[b2 * 4][c],     red[b2 * 4 + 1][c]),
                        fmaxf(red[b2 * 4 + 2][c], red[b2 * 4 + 3][c]));
        out[(long long)(tile * 2 + b2) * 64 + c] = m + __ldg(&conv_b[c]);
    }
}

extern "C" void kernel_launch(void* const* d_in, const int* in_sizes, int n_in,
                              void* d_out, int out_size) {
    const int*   path_input = (const int*)d_in[0];
    const int*   path_type  = (const int*)d_in[1];
    const float* tables     = (const float*)d_in[2];
    const float* conv_w     = (const float*)d_in[3];
    const float* conv_b     = (const float*)d_in[4];
    float* out = (float*)d_out;

    cudaFuncSetAttribute(path_emb_hmma,
                         cudaFuncAttributeMaxDynamicSharedMemorySize, SM_TOT);

    path_emb_hmma<<<4096, 256, SM_TOT>>>(path_input, path_type, tables,
                                         conv_w, conv_b, out);
}

// round 6
// speedup vs baseline: 4.5804x; 1.9523x over previous
#include <cuda_runtime.h>
#include <cuda_fp16.h>
#include <cstdint>

// Path_Embedding via mma.sync m16n8k16.f16 (2-term split: E = Eh+El in f16,
// W single f16). Per tile (2 output rows): S[128 x 64] logically, realized as
// dedup E (160 rows x 64k) with per-lane ldmatrix row addressing:
//   window w, tap0 -> e-row (b2,a,t=w); tap1 -> e-row (b2,a,t=w+1)  (+1 row)
// S = sum_taps sum_k (Eh+El)[row(tap)][k] * W[tap][o][k]
// then out[b][c] = bias[c] + max over the 64 (a,w)-rows of b.
// 256 thr / 8 warps (m16 each), 72.3KB smem -> 3 blocks/SM (24 warps).

#define VOCAB 100000
#define RSE 160        // e-row stride bytes (128B data + swizzle room)
#define RSW 144        // w-row stride bytes

#define EH_OFF  0      // 160*160 = 25600
#define EL_OFF  25600
#define W_OFF   51200  // 2 taps * 64 o * 144 = 18432
#define IDX_OFF 69632  // 160*4
#define RED_OFF 70272  // 8*64*4
#define SM_TOT  72320

typedef unsigned long long u64;

__device__ __forceinline__ uint32_t smem_u32(const void* p) {
    uint32_t a;
    asm("{ .reg .u64 t; cvta.to.shared.u64 t, %1; cvt.u32.u64 %0, t; }" : "=r"(a) : "l"(p));
    return a;
}

#define LDMX4(r, addr)                                                        \
    asm volatile("ldmatrix.sync.aligned.m8n8.x4.shared.b16 {%0,%1,%2,%3}, [%4];" \
        : "=r"((r)[0]), "=r"((r)[1]), "=r"((r)[2]), "=r"((r)[3]) : "r"(addr))

#define MMA(d, a, b0, b1)                                                     \
    asm volatile("mma.sync.aligned.m16n8k16.row.col.f32.f16.f16.f32 "         \
        "{%0,%1,%2,%3},{%4,%5,%6,%7},{%8,%9},{%0,%1,%2,%3};"                  \
        : "+f"((d)[0]), "+f"((d)[1]), "+f"((d)[2]), "+f"((d)[3])              \
        : "r"((a)[0]), "r"((a)[1]), "r"((a)[2]), "r"((a)[3]),                 \
          "r"(b0), "r"(b1))

// split 4 floats into packed f16x2 hi (returned) and lo residual (out-param)
__device__ __forceinline__ u64 pack_hi_lo(float x, float y, float z, float w,
                                          u64& lo_out) {
    __half2 h01 = __float22half2_rn(make_float2(x, y));
    __half2 h23 = __float22half2_rn(make_float2(z, w));
    float2 f01 = __half22float2(h01);
    float2 f23 = __half22float2(h23);
    __half2 l01 = __float22half2_rn(make_float2(x - f01.x, y - f01.y));
    __half2 l23 = __float22half2_rn(make_float2(z - f23.x, w - f23.y));
    uint32_t h0 = *reinterpret_cast<uint32_t*>(&h01);
    uint32_t h1 = *reinterpret_cast<uint32_t*>(&h23);
    uint32_t l0 = *reinterpret_cast<uint32_t*>(&l01);
    uint32_t l1 = *reinterpret_cast<uint32_t*>(&l23);
    lo_out = (u64)l0 | ((u64)l1 << 32);
    return (u64)h0 | ((u64)h1 << 32);
}

__global__ __launch_bounds__(256, 3) void path_emb_hmma(
    const int*   __restrict__ path_input,   // [8192,16,5]
    const int*   __restrict__ path_type,    // [5]
    const float* __restrict__ tables,       // [3,100000,64]
    const float* __restrict__ conv_w,       // [64,64,2]
    const float* __restrict__ conv_b,       // [64]
    float*       __restrict__ out)          // [8192,64]
{
    extern __shared__ char smem[];
    const uint32_t sb = smem_u32(smem);
    const int tid  = threadIdx.x;
    const int lane = tid & 31;
    const int wid  = tid >> 5;
    const int tile = blockIdx.x;

    int*  idx_s      = reinterpret_cast<int*>(smem + IDX_OFF);
    float (*red)[64] = reinterpret_cast<float(*)[64]>(smem + RED_OFF);

    // ---- stage indices (160 e-rows: 2 b x 16 a x 5 t) ----
    if (tid < 160) {
        int b2 = tid / 80, rr = tid % 80, a = rr / 5, t = rr % 5;
        int b = tile * 2 + b2, p = b & 15, nb = b >> 4;
        int raw = path_input[(((a << 9) + nb) * 16 + p) * 5 + t];
        idx_s[tid] = __ldg(&path_type[t]) * VOCAB + raw;
    }

    // ---- stage W (single f16): layout [tap][o][k64], stride 144B ----
    {
        const float2* cw2 = reinterpret_cast<const float2*>(conv_w);
        #pragma unroll
        for (int it = 0; it < 16; it++) {
            int i = tid + it * 256;          // i = o*64 + j
            int o = i >> 6, j = i & 63;
            float2 wv = cw2[i];              // (W0[o][j], W1[o][j])
            int ob = o * RSW + (((o >> 3) & 1) << 4) + j * 2;
            *reinterpret_cast<__half*>(smem + W_OFF + ob)        = __float2half_rn(wv.x);
            *reinterpret_cast<__half*>(smem + W_OFF + 9216 + ob) = __float2half_rn(wv.y);
        }
    }
    __syncthreads();

    // ---- gather E (160 rows x 16 float4), f16 hi/lo split, single store ----
    const float4* tab4 = reinterpret_cast<const float4*>(tables);
    #pragma unroll
    for (int g = 0; g < 10; g++) {
        int k = tid + g * 256;               // 2560 total
        int row = k >> 4, q = k & 15;
        float4 v = __ldg(&tab4[(long long)idx_s[row] * 16 + q]);
        u64 L, H = pack_hi_lo(v.x, v.y, v.z, v.w, L);
        int a = (row % 80) / 5;
        int off = row * RSE + ((a & 1) << 4) + q * 8;
        *reinterpret_cast<u64*>(smem + EH_OFF + off) = H;
        *reinterpret_cast<u64*>(smem + EL_OFF + off) = L;
    }
    __syncthreads();

    // ---- mma: warp owns m-rows [16*wid, 16*wid+16); m = b2*64 + a*4 + w ----
    uint32_t abase, boff;
    {
        int m  = wid * 16 + (lane & 15);
        int b2 = m >> 6, aa = (m >> 2) & 15, w = m & 3;
        int arow = b2 * 80 + aa * 5 + w;     // tap adds +1 row (same a, t<=4)
        abase = (uint32_t)(arow * RSE + ((aa & 1) << 4) + ((lane >> 4) << 4));
        int nrow = (lane & 7) + ((lane >> 4) << 3);
        boff = (uint32_t)(nrow * RSW + (((nrow >> 3) & 1) << 4)
                          + (((lane >> 3) & 1) << 4));
    }

    float d[8][4];
    #pragma unroll
    for (int nt = 0; nt < 8; nt++)
        #pragma unroll
        for (int r = 0; r < 4; r++) d[nt][r] = 0.f;

    #pragma unroll
    for (int tap = 0; tap < 2; tap++) {
        const uint32_t aH = sb + EH_OFF + abase + tap * RSE;
        const uint32_t aL = sb + EL_OFF + abase + tap * RSE;
        const uint32_t bW = sb + W_OFF + tap * 9216 + boff;
        #pragma unroll
        for (int ks = 0; ks < 4; ks++) {
            const uint32_t kb = ks * 32;     // 16 f16 per k-step
            uint32_t ah[4], al[4], bw[16];
            LDMX4(ah, aH + kb);
            LDMX4(al, aL + kb);
            #pragma unroll
            for (int g = 0; g < 4; g++) LDMX4(&bw[4 * g], bW + kb + g * 16 * RSW);
            #pragma unroll
            for (int nt = 0; nt < 8; nt++) {
                const int bi = (nt >> 1) * 4 + (nt & 1) * 2;
                MMA(d[nt], ah, bw[bi], bw[bi + 1]);   // Eh * W
                MMA(d[nt], al, bw[bi], bw[bi + 1]);   // El * W
            }
        }
    }

    // ---- epilogue: max over this warp's 16 m-rows per column ----
    #pragma unroll
    for (int nt = 0; nt < 8; nt++) {
        float v0 = fmaxf(d[nt][0], d[nt][2]);
        float v1 = fmaxf(d[nt][1], d[nt][3]);
        #pragma unroll
        for (int mask = 4; mask <= 16; mask <<= 1) {
            v0 = fmaxf(v0, __shfl_xor_sync(0xffffffffu, v0, mask));
            v1 = fmaxf(v1, __shfl_xor_sync(0xffffffffu, v1, mask));
        }
        if (lane < 4) {
            red[wid][nt * 8 + lane * 2]     = v0;
            red[wid][nt * 8 + lane * 2 + 1] = v1;
        }
    }
    __syncthreads();

    // ---- final: warps 0-3 -> b2=0, warps 4-7 -> b2=1 ----
    if (tid < 128) {
        int b2 = tid >> 6, c = tid & 63;
        float m = fmaxf(fmaxf(red[b2 * 4][c],     red[b2 * 4 + 1][c]),
                        fmaxf(red[b2 * 4 + 2][c], red[b2 * 4 + 3][c]));
        out[(long long)(tile * 2 + b2) * 64 + c] = m + __ldg(&conv_b[c]);
    }
}

extern "C" void kernel_launch(void* const* d_in, const int* in_sizes, int n_in,
                              void* d_out, int out_size) {
    const int*   path_input = (const int*)d_in[0];
    const int*   path_type  = (const int*)d_in[1];
    const float* tables     = (const float*)d_in[2];
    const float* conv_w     = (const float*)d_in[3];
    const float* conv_b     = (const float*)d_in[4];
    float* out = (float*)d_out;

    cudaFuncSetAttribute(path_emb_hmma,
                         cudaFuncAttributeMaxDynamicSharedMemorySize, SM_TOT);

    path_emb_hmma<<<4096, 256, SM_TOT>>>(path_input, path_type, tables,
                                         conv_w, conv_b, out);
}

// round 7
// speedup vs baseline: 5.9291x; 1.2945x over previous
#include <cuda_runtime.h>
#include <cuda_fp16.h>
#include <cstdint>

// Path_Embedding via mma.sync m16n8k16.f16, single-f16 operands (no split).
// Per tile (2 output rows): S[128 x 64] = E'(128x128) @ W'^T, realized with
// dedup E (160 rows x 64k) + per-lane ldmatrix row addressing (tap = +1 row).
// Statistical error cancellation over k=128 keeps rel_err ~1e-4 (measured
// 4.8e-5 with W-only f16 in R6).
// 256 thr / 8 warps (m16 each); 46.7KB smem + <=64 regs -> 4 blocks/SM (occ 50%).

#define VOCAB 100000
#define RSE 160        // e-row stride bytes (+16B nudge when a odd: conflict-free)
#define RSW 144        // w-row stride bytes (+16B nudge when (o>>3)&1)

#define E_OFF   0      // 160*160 = 25600
#define W_OFF   25600  // 2 taps * 64 * 144 = 18432
#define IDX_OFF 44032  // 160*4
#define RED_OFF 44672  // 8*64*4
#define SM_TOT  46720

typedef unsigned long long u64;

__device__ __forceinline__ uint32_t smem_u32(const void* p) {
    uint32_t a;
    asm("{ .reg .u64 t; cvta.to.shared.u64 t, %1; cvt.u32.u64 %0, t; }" : "=r"(a) : "l"(p));
    return a;
}

#define LDMX4(r, addr)                                                        \
    asm volatile("ldmatrix.sync.aligned.m8n8.x4.shared.b16 {%0,%1,%2,%3}, [%4];" \
        : "=r"((r)[0]), "=r"((r)[1]), "=r"((r)[2]), "=r"((r)[3]) : "r"(addr))

#define MMA(d, a, b0, b1)                                                     \
    asm volatile("mma.sync.aligned.m16n8k16.row.col.f32.f16.f16.f32 "         \
        "{%0,%1,%2,%3},{%4,%5,%6,%7},{%8,%9},{%0,%1,%2,%3};"                  \
        : "+f"((d)[0]), "+f"((d)[1]), "+f"((d)[2]), "+f"((d)[3])              \
        : "r"((a)[0]), "r"((a)[1]), "r"((a)[2]), "r"((a)[3]),                 \
          "r"(b0), "r"(b1))

// pack 4 floats -> 2x f16x2 (one u64)
__device__ __forceinline__ u64 pack4(float x, float y, float z, float w) {
    __half2 h01 = __float22half2_rn(make_float2(x, y));
    __half2 h23 = __float22half2_rn(make_float2(z, w));
    uint32_t h0 = *reinterpret_cast<uint32_t*>(&h01);
    uint32_t h1 = *reinterpret_cast<uint32_t*>(&h23);
    return (u64)h0 | ((u64)h1 << 32);
}

__global__ __launch_bounds__(256, 4) void path_emb_hmma(
    const int*   __restrict__ path_input,   // [8192,16,5]
    const int*   __restrict__ path_type,    // [5]
    const float* __restrict__ tables,       // [3,100000,64]
    const float* __restrict__ conv_w,       // [64,64,2]
    const float* __restrict__ conv_b,       // [64]
    float*       __restrict__ out)          // [8192,64]
{
    extern __shared__ char smem[];
    const uint32_t sb = smem_u32(smem);
    const int tid  = threadIdx.x;
    const int lane = tid & 31;
    const int wid  = tid >> 5;
    const int tile = blockIdx.x;

    int*  idx_s      = reinterpret_cast<int*>(smem + IDX_OFF);
    float (*red)[64] = reinterpret_cast<float(*)[64]>(smem + RED_OFF);

    // ---- stage indices (160 e-rows: 2 b x 16 a x 5 t) ----
    if (tid < 160) {
        int b2 = tid / 80, rr = tid % 80, a = rr / 5, t = rr % 5;
        int b = tile * 2 + b2, p = b & 15, nb = b >> 4;
        int raw = path_input[(((a << 9) + nb) * 16 + p) * 5 + t];
        idx_s[tid] = __ldg(&path_type[t]) * VOCAB + raw;
    }

    // ---- stage W (f16): [tap][o][k64], stride 144B + o-group nudge ----
    {
        const float2* cw2 = reinterpret_cast<const float2*>(conv_w);
        #pragma unroll
        for (int it = 0; it < 16; it++) {
            int i = tid + it * 256;          // i = o*64 + j
            int o = i >> 6, j = i & 63;
            float2 wv = cw2[i];              // (W0[o][j], W1[o][j])
            int ob = o * RSW + (((o >> 3) & 1) << 4) + j * 2;
            *reinterpret_cast<__half*>(smem + W_OFF + ob)        = __float2half_rn(wv.x);
            *reinterpret_cast<__half*>(smem + W_OFF + 9216 + ob) = __float2half_rn(wv.y);
        }
    }
    __syncthreads();

    // ---- gather E (160 rows x 16 float4) -> f16, single store ----
    const float4* tab4 = reinterpret_cast<const float4*>(tables);
    #pragma unroll
    for (int g = 0; g < 10; g++) {
        int k = tid + g * 256;               // 2560 total
        int row = k >> 4, q = k & 15;
        float4 v = __ldg(&tab4[(long long)idx_s[row] * 16 + q]);
        u64 H = pack4(v.x, v.y, v.z, v.w);
        int a = (row % 80) / 5;
        int off = row * RSE + ((a & 1) << 4) + q * 8;
        *reinterpret_cast<u64*>(smem + E_OFF + off) = H;
    }
    __syncthreads();

    // ---- mma: warp owns m-rows [16*wid, 16*wid+16); m = b2*64 + a*4 + w ----
    uint32_t abase, boff;
    {
        int m  = wid * 16 + (lane & 15);
        int b2 = m >> 6, aa = (m >> 2) & 15, w = m & 3;
        int arow = b2 * 80 + aa * 5 + w;     // tap adds +1 row (same a)
        abase = (uint32_t)(arow * RSE + ((aa & 1) << 4) + ((lane >> 4) << 4));
        int nrow = (lane & 7) + ((lane >> 4) << 3);
        boff = (uint32_t)(nrow * RSW + (((nrow >> 3) & 1) << 4)
                          + (((lane >> 3) & 1) << 4));
    }

    float d[8][4];
    #pragma unroll
    for (int nt = 0; nt < 8; nt++)
        #pragma unroll
        for (int r = 0; r < 4; r++) d[nt][r] = 0.f;

    #pragma unroll
    for (int tap = 0; tap < 2; tap++) {
        const uint32_t aE = sb + E_OFF + abase + tap * RSE;
        const uint32_t bW = sb + W_OFF + tap * 9216 + boff;
        #pragma unroll
        for (int ks = 0; ks < 4; ks++) {
            const uint32_t kb = ks * 32;     // 16 f16 per k-step
            uint32_t ah[4];
            LDMX4(ah, aE + kb);
            #pragma unroll
            for (int g = 0; g < 4; g++) {    // B live regs: 4 (one group at a time)
                uint32_t bw[4];
                LDMX4(bw, bW + kb + g * 16 * RSW);
                MMA(d[2 * g],     ah, bw[0], bw[1]);
                MMA(d[2 * g + 1], ah, bw[2], bw[3]);
            }
        }
    }

    // ---- epilogue: max over this warp's 16 m-rows per column ----
    #pragma unroll
    for (int nt = 0; nt < 8; nt++) {
        float v0 = fmaxf(d[nt][0], d[nt][2]);
        float v1 = fmaxf(d[nt][1], d[nt][3]);
        #pragma unroll
        for (int mask = 4; mask <= 16; mask <<= 1) {
            v0 = fmaxf(v0, __shfl_xor_sync(0xffffffffu, v0, mask));
            v1 = fmaxf(v1, __shfl_xor_sync(0xffffffffu, v1, mask));
        }
        if (lane < 4) {
            red[wid][nt * 8 + lane * 2]     = v0;
            red[wid][nt * 8 + lane * 2 + 1] = v1;
        }
    }
    __syncthreads();

    // ---- final: warps 0-3 -> b2=0, warps 4-7 -> b2=1 ----
    if (tid < 128) {
        int b2 = tid >> 6, c = tid & 63;
        float m = fmaxf(fmaxf(red[b2 * 4][c],     red[b2 * 4 + 1][c]),
                        fmaxf(red[b2 * 4 + 2][c], red[b2 * 4 + 3][c]));
        out[(long long)(tile * 2 + b2) * 64 + c] = m + __ldg(&conv_b[c]);
    }
}

extern "C" void kernel_launch(void* const* d_in, const int* in_sizes, int n_in,
                              void* d_out, int out_size) {
    const int*   path_input = (const int*)d_in[0];
    const int*   path_type  = (const int*)d_in[1];
    const float* tables     = (const float*)d_in[2];
    const float* conv_w     = (const float*)d_in[3];
    const float* conv_b     = (const float*)d_in[4];
    float* out = (float*)d_out;

    cudaFuncSetAttribute(path_emb_hmma,
                         cudaFuncAttributeMaxDynamicSharedMemorySize, SM_TOT);

    path_emb_hmma<<<4096, 256, SM_TOT>>>(path_input, path_type, tables,
                                         conv_w, conv_b, out);
}